// round 5
// baseline (speedup 1.0000x reference)
#include <cuda_runtime.h>
#include <cuda_fp16.h>
#include <stdint.h>

#define D_MODEL 2048
#define H_FF    1408
#define NE      8
#define NTOK    8192
#define SLOTS   16384
#define CAP     2048
#define BK      32                 // halfs per k-tile (64B rows)

#define NT1     (D_MODEL / BK)     // 64
#define NT3     (H_FF / BK)        // 44

// smem stage layout (bytes): rows padded to 80B (20 words; conflict-free)
#define G1_BG   10240
#define G1_BU   20480
#define G3_B    10240
#define STG     30720
#define SMEM_SZ (3 * STG)          // 92160

// ---------------- scratch ----------------
__device__ int    g_cnt[NE];
__device__ int    g_tok[SLOTS];
__device__ float  g_scr[SLOTS];
__device__ __half g_xh [(size_t)NTOK * D_MODEL];           // fp16 row-major [tok][d]
__device__ __half g_Wgh[(size_t)NE * H_FF * D_MODEL];      // [e][h][d]  (transposed)
__device__ __half g_Wuh[(size_t)NE * H_FF * D_MODEL];      // [e][h][d]
__device__ __half g_Wdh[(size_t)NE * D_MODEL * H_FF];      // [e][d][h]  (transposed)
__device__ __half g_Hh [(size_t)SLOTS * H_FF];             // [slot][h]

// ---------------- helpers ----------------
__device__ __forceinline__ uint32_t smem_u32(const void* p) {
    uint32_t a;
    asm("{ .reg .u64 t; cvta.to.shared.u64 t, %1; cvt.u32.u64 %0, t; }" : "=r"(a) : "l"(p));
    return a;
}
__device__ __forceinline__ void cp16(uint32_t dst, const void* src) {
    asm volatile("cp.async.cg.shared.global [%0], [%1], 16;" :: "r"(dst), "l"(src));
}
__device__ __forceinline__ void cp_commit() { asm volatile("cp.async.commit_group;"); }
__device__ __forceinline__ void cp_wait1() { asm volatile("cp.async.wait_group 1;"); }
__device__ __forceinline__ void cp_wait0() { asm volatile("cp.async.wait_group 0;"); }

__device__ __forceinline__ void mma16(float* d, const uint32_t* a, const uint32_t* b) {
    asm volatile(
        "mma.sync.aligned.m16n8k16.row.col.f32.f16.f16.f32 "
        "{%0,%1,%2,%3}, {%4,%5,%6,%7}, {%8,%9}, {%0,%1,%2,%3};\n"
        : "+f"(d[0]), "+f"(d[1]), "+f"(d[2]), "+f"(d[3])
        : "r"(a[0]), "r"(a[1]), "r"(a[2]), "r"(a[3]), "r"(b[0]), "r"(b[1]));
}
__device__ __forceinline__ void ldmx4(uint32_t& r0, uint32_t& r1, uint32_t& r2, uint32_t& r3,
                                      uint32_t a) {
    asm volatile("ldmatrix.sync.aligned.m8n8.x4.shared.b16 {%0,%1,%2,%3}, [%4];"
        : "=r"(r0), "=r"(r1), "=r"(r2), "=r"(r3) : "r"(a));
}

// ---------------- pre-pass kernels ----------------
__global__ void zero_kernel(float4* __restrict__ y, int n4) {
    int i = blockIdx.x * blockDim.x + threadIdx.x;
    if (i < n4) y[i] = make_float4(0.f, 0.f, 0.f, 0.f);
    if (blockIdx.x == 0 && threadIdx.x < NE) g_cnt[threadIdx.x] = 0;
}

__global__ void route_kernel(const int* __restrict__ idx, const float* __restrict__ scr) {
    int s = blockIdx.x * blockDim.x + threadIdx.x;
    if (s < SLOTS) {
        int e = idx[s];
        int p = atomicAdd(&g_cnt[e], 1);
        g_tok[e * CAP + p] = s >> 1;     // TOP_K = 2
        g_scr[e * CAP + p] = scr[s];
    }
}

__global__ void cvtx_kernel(const float4* __restrict__ src, uint2* __restrict__ dst, int n4) {
    int i = blockIdx.x * blockDim.x + threadIdx.x;
    if (i < n4) {
        float4 v = src[i];
        __half2 h01 = __floats2half2_rn(v.x, v.y);
        __half2 h23 = __floats2half2_rn(v.z, v.w);
        uint2 o;
        o.x = *(uint32_t*)&h01;
        o.y = *(uint32_t*)&h23;
        dst[i] = o;
    }
}

// transpose+convert body: src [K][N] fp32 -> dst [N][K] fp16, tile 64k x 32n
__device__ __forceinline__ void trcvt_body(const float* S, __half* D, int K, int N,
                                           int k0, int n0, int tid) {
    __shared__ float t[64][33];
    #pragma unroll
    for (int it = 0; it < 2; it++) {
        int idx = tid + it * 256;
        int kr = idx >> 3, c4 = (idx & 7) * 4;
        float4 v = *(const float4*)(S + (size_t)(k0 + kr) * N + n0 + c4);
        t[kr][c4] = v.x; t[kr][c4 + 1] = v.y; t[kr][c4 + 2] = v.z; t[kr][c4 + 3] = v.w;
    }
    __syncthreads();
    #pragma unroll
    for (int it = 0; it < 4; it++) {
        int idx = tid + it * 256;
        int n = idx >> 5, k2 = idx & 31;
        __half2 h = __floats2half2_rn(t[2 * k2][n], t[2 * k2 + 1][n]);
        ((__half2*)(D + (size_t)(n0 + n) * K + k0))[k2] = h;
    }
}

// Wg and Wu in one launch: z in [0,16), matrix = z>>3, e = z&7
__global__ void trcvtGU_kernel(const float* __restrict__ Wg, const float* __restrict__ Wu,
                               __half* __restrict__ dg, __half* __restrict__ du) {
    const int z = blockIdx.z;
    const int e = z & 7;
    const float* S = ((z < 8) ? Wg : Wu) + (size_t)e * D_MODEL * H_FF;
    __half* D = ((z < 8) ? dg : du) + (size_t)e * H_FF * D_MODEL;
    trcvt_body(S, D, D_MODEL, H_FF, blockIdx.x * 64, blockIdx.y * 32, threadIdx.x);
}

__global__ void trcvtD_kernel(const float* __restrict__ Wd, __half* __restrict__ dd) {
    const int e = blockIdx.z;
    trcvt_body(Wd + (size_t)e * H_FF * D_MODEL, dd + (size_t)e * D_MODEL * H_FF,
               H_FF, D_MODEL, blockIdx.x * 64, blockIdx.y * 32, threadIdx.x);
}

// ---------------------------------------------------------------------------
// GEMM1+2 fused (fp16). CTA: 128 slots x 128 h for BOTH gate and up.
// 8 warps 2x4, warp 64x32 per matrix. ldmatrix fragment loads, BK=32,
// 3-stage cp.async pipeline with prefetch issued before MMA.
// ---------------------------------------------------------------------------
__global__ void __launch_bounds__(256, 1) g1_kernel() {
    extern __shared__ uint32_t sm[];
    const int tid = threadIdx.x, lane = tid & 31, w = tid >> 5;
    const int wm = w >> 2, wn = w & 3;
    const int ql = lane >> 2, qc = lane & 3;
    const int e = blockIdx.z, bm = blockIdx.x, bn = blockIdx.y;
    const uint32_t sbase = smem_u32(sm);

    // ldmatrix per-thread address components
    const uint32_t aOff = (wm * 64 + (lane & 15)) * 80 + (lane >> 4) * 16;
    const uint32_t bOff = (wn * 32 + (lane & 7) + ((lane >> 4) * 8)) * 80
                        + (((lane >> 3) & 1) * 16);

    // loader: thread covers rows r4 and r4+64, 16B chunk ck
    const int r4 = tid >> 2, ck = tid & 3;
    const __half* ap0 = g_xh + (size_t)g_tok[e * CAP + bm * 128 + r4] * D_MODEL + ck * 8;
    const __half* ap1 = g_xh + (size_t)g_tok[e * CAP + bm * 128 + r4 + 64] * D_MODEL + ck * 8;
    const size_t bbase = ((size_t)e * H_FF + (size_t)bn * 128 + r4) * D_MODEL + ck * 8;
    const __half* gp0 = g_Wgh + bbase;
    const __half* gp1 = g_Wgh + bbase + (size_t)64 * D_MODEL;
    const __half* up0 = g_Wuh + bbase;
    const __half* up1 = g_Wuh + bbase + (size_t)64 * D_MODEL;
    const uint32_t ad0 = sbase + r4 * 80 + ck * 16, ad1 = ad0 + 64 * 80;
    const uint32_t gd0 = sbase + G1_BG + r4 * 80 + ck * 16, gd1 = gd0 + 64 * 80;
    const uint32_t ud0 = sbase + G1_BU + r4 * 80 + ck * 16, ud1 = ud0 + 64 * 80;

    float accg[4][4][4], accu[4][4][4];
    #pragma unroll
    for (int mi = 0; mi < 4; mi++)
        #pragma unroll
        for (int ni = 0; ni < 4; ni++)
            #pragma unroll
            for (int q = 0; q < 4; q++) { accg[mi][ni][q] = 0.f; accu[mi][ni][q] = 0.f; }

    #pragma unroll
    for (int s = 0; s < 2; s++) {
        const uint32_t so = s * STG;
        const int ko = s * BK;
        cp16(ad0 + so, ap0 + ko); cp16(ad1 + so, ap1 + ko);
        cp16(gd0 + so, gp0 + ko); cp16(gd1 + so, gp1 + ko);
        cp16(ud0 + so, up0 + ko); cp16(ud1 + so, up1 + ko);
        cp_commit();
    }

    for (int kt = 0; kt < NT1; kt++) {
        const int s = kt % 3;
        if (kt >= NT1 - 2) cp_wait0(); else cp_wait1();
        __syncthreads();

        // prefetch kt+2 (stage (kt+2)%3 was fully consumed in iteration kt-1)
        if (kt + 2 < NT1) {
            const uint32_t so = ((kt + 2) % 3) * STG;
            const int ko = (kt + 2) * BK;
            cp16(ad0 + so, ap0 + ko); cp16(ad1 + so, ap1 + ko);
            cp16(gd0 + so, gp0 + ko); cp16(gd1 + so, gp1 + ko);
            cp16(ud0 + so, up0 + ko); cp16(ud1 + so, up1 + ko);
            cp_commit();
        }

        const uint32_t stB = sbase + s * STG;
        #pragma unroll
        for (int kk = 0; kk < 2; kk++) {
            uint32_t af[4][4];
            #pragma unroll
            for (int mi = 0; mi < 4; mi++)
                ldmx4(af[mi][0], af[mi][1], af[mi][2], af[mi][3],
                      stB + aOff + mi * 1280 + kk * 32);
            #pragma unroll
            for (int np = 0; np < 2; np++) {
                uint32_t bg[4], bu[4];
                ldmx4(bg[0], bg[1], bg[2], bg[3], stB + G1_BG + bOff + np * 1280 + kk * 32);
                ldmx4(bu[0], bu[1], bu[2], bu[3], stB + G1_BU + bOff + np * 1280 + kk * 32);
                #pragma unroll
                for (int mi = 0; mi < 4; mi++) {
                    mma16(accg[mi][np * 2],     af[mi], bg);
                    mma16(accg[mi][np * 2 + 1], af[mi], bg + 2);
                    mma16(accu[mi][np * 2],     af[mi], bu);
                    mma16(accu[mi][np * 2 + 1], af[mi], bu + 2);
                }
            }
        }
    }

    // epilogue: h = silu(g)*u -> fp16 H
    const size_t rowBase = (size_t)e * CAP + (size_t)bm * 128;
    const int colBase = bn * 128 + wn * 32;
    #pragma unroll
    for (int mi = 0; mi < 4; mi++)
        #pragma unroll
        for (int ni = 0; ni < 4; ni++)
            #pragma unroll
            for (int q2 = 0; q2 < 2; q2++) {
                const int r = wm * 64 + mi * 16 + ql + q2 * 8;
                float g0 = accg[mi][ni][q2 * 2],     u0 = accu[mi][ni][q2 * 2];
                float g1 = accg[mi][ni][q2 * 2 + 1], u1 = accu[mi][ni][q2 * 2 + 1];
                float h0 = (g0 / (1.f + __expf(-g0))) * u0;
                float h1 = (g1 / (1.f + __expf(-g1))) * u1;
                *(__half2*)(g_Hh + (rowBase + r) * H_FF + colBase + ni * 8 + 2 * qc) =
                    __floats2half2_rn(h0, h1);
            }
}

// ---------------------------------------------------------------------------
// GEMM3 (fp16): y[tok] += score * (H @ Wd^T). CTA: 128 slots x 256 d.
// Warp tile 64x64. K = H_FF, BK=32.
// ---------------------------------------------------------------------------
__global__ void __launch_bounds__(256, 1) g3_kernel(float* __restrict__ y) {
    extern __shared__ uint32_t sm[];
    __shared__ int   sTok[128];
    __shared__ float sScr[128];
    const int tid = threadIdx.x, lane = tid & 31, w = tid >> 5;
    const int wm = w >> 2, wn = w & 3;
    const int ql = lane >> 2, qc = lane & 3;
    const int e = blockIdx.z, bm = blockIdx.x, bn = blockIdx.y;
    const uint32_t sbase = smem_u32(sm);

    if (tid < 128) {
        int slot = e * CAP + bm * 128 + tid;
        sTok[tid] = g_tok[slot];
        sScr[tid] = g_scr[slot];
    }

    const uint32_t aOff = (wm * 64 + (lane & 15)) * 80 + (lane >> 4) * 16;
    const uint32_t bOff = (wn * 64 + (lane & 7) + ((lane >> 4) * 8)) * 80
                        + (((lane >> 3) & 1) * 16);

    const int r4 = tid >> 2, ck = tid & 3;
    const __half* ap0 = g_Hh + ((size_t)e * CAP + (size_t)bm * 128 + r4) * H_FF + ck * 8;
    const __half* ap1 = ap0 + (size_t)64 * H_FF;
    const size_t bbase = ((size_t)e * D_MODEL + (size_t)bn * 256 + r4) * H_FF + ck * 8;
    const __half* bp0 = g_Wdh + bbase;
    const __half* bp1 = g_Wdh + bbase + (size_t)64 * H_FF;
    const __half* bp2 = g_Wdh + bbase + (size_t)128 * H_FF;
    const __half* bp3 = g_Wdh + bbase + (size_t)192 * H_FF;
    const uint32_t ad0 = sbase + r4 * 80 + ck * 16, ad1 = ad0 + 64 * 80;
    const uint32_t bd0 = sbase + G3_B + r4 * 80 + ck * 16;
    const uint32_t bd1 = bd0 + 64 * 80, bd2 = bd0 + 128 * 80, bd3 = bd0 + 192 * 80;

    float acc[4][8][4];
    #pragma unroll
    for (int mi = 0; mi < 4; mi++)
        #pragma unroll
        for (int ni = 0; ni < 8; ni++)
            #pragma unroll
            for (int q = 0; q < 4; q++) acc[mi][ni][q] = 0.f;

    #pragma unroll
    for (int s = 0; s < 2; s++) {
        const uint32_t so = s * STG;
        const int ko = s * BK;
        cp16(ad0 + so, ap0 + ko); cp16(ad1 + so, ap1 + ko);
        cp16(bd0 + so, bp0 + ko); cp16(bd1 + so, bp1 + ko);
        cp16(bd2 + so, bp2 + ko); cp16(bd3 + so, bp3 + ko);
        cp_commit();
    }

    for (int kt = 0; kt < NT3; kt++) {
        const int s = kt % 3;
        if (kt >= NT3 - 2) cp_wait0(); else cp_wait1();
        __syncthreads();

        if (kt + 2 < NT3) {
            const uint32_t so = ((kt + 2) % 3) * STG;
            const int ko = (kt + 2) * BK;
            cp16(ad0 + so, ap0 + ko); cp16(ad1 + so, ap1 + ko);
            cp16(bd0 + so, bp0 + ko); cp16(bd1 + so, bp1 + ko);
            cp16(bd2 + so, bp2 + ko); cp16(bd3 + so, bp3 + ko);
            cp_commit();
        }

        const uint32_t stB = sbase + s * STG;
        #pragma unroll
        for (int kk = 0; kk < 2; kk++) {
            uint32_t af[4][4];
            #pragma unroll
            for (int mi = 0; mi < 4; mi++)
                ldmx4(af[mi][0], af[mi][1], af[mi][2], af[mi][3],
                      stB + aOff + mi * 1280 + kk * 32);
            #pragma unroll
            for (int np = 0; np < 4; np++) {
                uint32_t bf[4];
                ldmx4(bf[0], bf[1], bf[2], bf[3], stB + G3_B + bOff + np * 1280 + kk * 32);
                #pragma unroll
                for (int mi = 0; mi < 4; mi++) {
                    mma16(acc[mi][np * 2],     af[mi], bf);
                    mma16(acc[mi][np * 2 + 1], af[mi], bf + 2);
                }
            }
        }
    }

    // epilogue: scale + atomic combine
    const int colBase = bn * 256 + wn * 64;
    #pragma unroll
    for (int mi = 0; mi < 4; mi++) {
        #pragma unroll
        for (int q2 = 0; q2 < 2; q2++) {
            const int r = wm * 64 + mi * 16 + ql + q2 * 8;
            const float sc = sScr[r];
            float* yrow = y + (size_t)sTok[r] * D_MODEL + colBase;
            #pragma unroll
            for (int ni = 0; ni < 8; ni++) {
                const int n0 = ni * 8 + 2 * qc;
                atomicAdd(yrow + n0,     acc[mi][ni][q2 * 2]     * sc);
                atomicAdd(yrow + n0 + 1, acc[mi][ni][q2 * 2 + 1] * sc);
            }
        }
    }
}

// ---------------------------------------------------------------------------
extern "C" void kernel_launch(void* const* d_in, const int* in_sizes, int n_in,
                              void* d_out, int out_size) {
    (void)in_sizes; (void)n_in; (void)out_size;
    const float* x   = (const float*)d_in[0];
    const int*   idx = (const int*)d_in[1];
    const float* scr = (const float*)d_in[2];
    const float* Wg  = (const float*)d_in[3];
    const float* Wu  = (const float*)d_in[4];
    const float* Wd  = (const float*)d_in[5];
    float* y = (float*)d_out;

    const int n4x = NTOK * D_MODEL / 4;
    zero_kernel<<<(n4x + 255) / 256, 256>>>((float4*)y, n4x);
    route_kernel<<<SLOTS / 256, 256>>>(idx, scr);

    __half* gx; cudaGetSymbolAddress((void**)&gx, g_xh);
    __half* gg; cudaGetSymbolAddress((void**)&gg, g_Wgh);
    __half* gu; cudaGetSymbolAddress((void**)&gu, g_Wuh);
    __half* gd; cudaGetSymbolAddress((void**)&gd, g_Wdh);

    cvtx_kernel<<<(n4x + 255) / 256, 256>>>((const float4*)x, (uint2*)gx, n4x);
    dim3 tgu(D_MODEL / 64, H_FF / 32, 2 * NE);   // (32, 44, 16)
    trcvtGU_kernel<<<tgu, 256>>>(Wg, Wu, gg, gu);
    dim3 tgd(H_FF / 64, D_MODEL / 32, NE);       // (22, 64, 8)
    trcvtD_kernel<<<tgd, 256>>>(Wd, gd);

    cudaFuncSetAttribute(g1_kernel, cudaFuncAttributeMaxDynamicSharedMemorySize, SMEM_SZ);
    cudaFuncSetAttribute(g3_kernel, cudaFuncAttributeMaxDynamicSharedMemorySize, SMEM_SZ);

    dim3 grid1(CAP / 128, H_FF / 128, NE);    // (16, 11, 8)
    g1_kernel<<<grid1, 256, SMEM_SZ>>>();
    dim3 grid3(CAP / 128, D_MODEL / 256, NE); // (16, 8, 8)
    g3_kernel<<<grid3, 256, SMEM_SZ>>>(y);
}